// round 5
// baseline (speedup 1.0000x reference)
#include <cuda_runtime.h>
#include <cuda_bf16.h>
#include <cstdint>

// HashEmbedding gather: out[row,:] = embedding[hashed_ids[row],:]
// rows = 32768, D = 1024 fp32 = 4096 B per row.
//
// R5: persistent warp-streams with 1-row software pipeline.
// Each warp owns a strided sequence of rows. Per iteration it:
//   1. issues the 4x32B gathers for row i+1 (using id prefetched last iter)
//   2. prefetches the id for row i+2
//   3. stores row i (data already resident in registers)
// so the store stream never waits on gather latency.
// Reads use L2::evict_last (pin 40MB table in L2); stores are plain
// (streaming hint measured slower in R2).

static constexpr int THREADS = 256;          // 8 warps per block
static constexpr int BLOCKS  = 444;          // ~3 per SM (148 SMs)
static constexpr int ROW_BYTES = 4096;

struct alignas(32) F8 { float4 lo, hi; };

__device__ __forceinline__ F8 ldg256_el(const char* p)
{
    F8 v;
    asm volatile("ld.global.nc.L2::evict_last.v8.f32 "
                 "{%0,%1,%2,%3,%4,%5,%6,%7}, [%8];"
                 : "=f"(v.lo.x), "=f"(v.lo.y), "=f"(v.lo.z), "=f"(v.lo.w),
                   "=f"(v.hi.x), "=f"(v.hi.y), "=f"(v.hi.z), "=f"(v.hi.w)
                 : "l"(p));
    return v;
}

__device__ __forceinline__ void stg256(char* p, const F8& v)
{
    asm volatile("st.global.v8.f32 [%0], {%1,%2,%3,%4,%5,%6,%7,%8};"
                 :: "l"(p),
                    "f"(v.lo.x), "f"(v.lo.y), "f"(v.lo.z), "f"(v.lo.w),
                    "f"(v.hi.x), "f"(v.hi.y), "f"(v.hi.z), "f"(v.hi.w)
                 : "memory");
}

__global__ void __launch_bounds__(THREADS)
hash_embedding_gather(const int* __restrict__ hashed_ids,
                      const char* __restrict__ emb,
                      char* __restrict__ out,
                      int nrows)
{
    const int warp   = blockIdx.x * (THREADS / 32) + (threadIdx.x >> 5);
    const int lane   = threadIdx.x & 31;
    const int nwarps = gridDim.x * (THREADS / 32);
    const int loff   = lane * 32;              // 32 lanes x 32B x 4 = 4KB row

    int row = warp;
    if (row >= nrows) return;

    // ---- prologue: gather row, prefetch id of row+nwarps ----
    int id0 = __ldg(hashed_ids + row);
    {
        const char* s = emb + (size_t)id0 * ROW_BYTES + loff;
        // fallthrough into pipeline with these in 'cur'
        F8 c0 = ldg256_el(s);
        F8 c1 = ldg256_el(s + 1024);
        F8 c2 = ldg256_el(s + 2048);
        F8 c3 = ldg256_el(s + 3072);

        int  row_n  = row + nwarps;
        int  id_n   = (row_n < nrows) ? __ldg(hashed_ids + row_n) : 0;

        for (;;) {
            char* dst = out + (size_t)row * ROW_BYTES + loff;

            if (row_n < nrows) {
                // 1) gathers for the NEXT row (independent of stores below)
                const char* sn = emb + (size_t)id_n * ROW_BYTES + loff;
                F8 n0 = ldg256_el(sn);
                F8 n1 = ldg256_el(sn + 1024);
                F8 n2 = ldg256_el(sn + 2048);
                F8 n3 = ldg256_el(sn + 3072);

                // 2) prefetch id two rows ahead
                int row_nn = row_n + nwarps;
                int id_nn  = (row_nn < nrows) ? __ldg(hashed_ids + row_nn) : 0;

                // 3) stores for the CURRENT row (data already in regs)
                stg256(dst,        c0);
                stg256(dst + 1024, c1);
                stg256(dst + 2048, c2);
                stg256(dst + 3072, c3);

                c0 = n0; c1 = n1; c2 = n2; c3 = n3;
                row = row_n; row_n = row_nn; id_n = id_nn;
            } else {
                stg256(dst,        c0);
                stg256(dst + 1024, c1);
                stg256(dst + 2048, c2);
                stg256(dst + 3072, c3);
                break;
            }
        }
    }
}

extern "C" void kernel_launch(void* const* d_in, const int* in_sizes, int n_in,
                              void* d_out, int out_size)
{
    // metadata order: input_ids (unused), hashed_ids (int32), embedding (fp32)
    const int*  hashed_ids = (const int*)d_in[1];
    const char* emb        = (const char*)d_in[2];
    char*       out        = (char*)d_out;

    int nrows = in_sizes[1];   // 32768

    hash_embedding_gather<<<BLOCKS, THREADS>>>(hashed_ids, emb, out, nrows);
}

// round 6
// speedup vs baseline: 1.0369x; 1.0369x over previous
#include <cuda_runtime.h>
#include <cuda_bf16.h>
#include <cstdint>

// HashEmbedding gather via TMA bulk-copy DMA pipeline.
// out[row,:] = embedding[hashed_ids[row],:], 32768 rows x 4096 B.
//
// R6: SMs only orchestrate; all data moves via cp.async.bulk (1D, no
// tensormap). Per CTA: 3-stage x 32KB SMEM ring. Each stage is filled
// by 8 independent 4KB gathers (one per row id) tracked by one mbarrier
// (expect_tx = 32KB), then drained by ONE contiguous 32KB bulk store
// (rows in a chunk are consecutive). bulk_group completes in commit
// order, so wait_group<1> before refilling the stage stored last
// iteration guarantees its SMEM is free. 296 persistent CTAs (2/SM),
// 1 warp each, only lane 0 issues.

static constexpr int ROW_BYTES   = 4096;
static constexpr int CHUNK_ROWS  = 8;
static constexpr int CHUNK_BYTES = ROW_BYTES * CHUNK_ROWS;   // 32768
static constexpr int NSTAGES     = 3;
static constexpr int CTAS        = 296;                      // 2 per SM
static constexpr int STAGE_OFF   = 1024;                     // mbarriers below
static constexpr int SMEM_BYTES  = STAGE_OFF + NSTAGES * CHUNK_BYTES;

__device__ __forceinline__ uint32_t smem_u32(const void* p)
{
    uint32_t a;
    asm("{ .reg .u64 t; cvta.to.shared.u64 t, %1; cvt.u32.u64 %0, t; }"
        : "=r"(a) : "l"(p));
    return a;
}

__device__ __forceinline__ void mbar_init(uint32_t mbar, uint32_t count)
{
    asm volatile("mbarrier.init.shared.b64 [%0], %1;" :: "r"(mbar), "r"(count) : "memory");
}

__device__ __forceinline__ void mbar_expect_tx(uint32_t mbar, uint32_t bytes)
{
    asm volatile("mbarrier.arrive.expect_tx.shared.b64 _, [%0], %1;"
                 :: "r"(mbar), "r"(bytes) : "memory");
}

__device__ __forceinline__ void mbar_wait(uint32_t mbar, uint32_t parity)
{
    asm volatile(
        "{\n\t"
        ".reg .pred P;\n\t"
        "WAIT_%=:\n\t"
        "mbarrier.try_wait.parity.shared.b64 P, [%0], %1, 0x989680;\n\t"
        "@P bra.uni DONE_%=;\n\t"
        "bra.uni WAIT_%=;\n\t"
        "DONE_%=:\n\t"
        "}"
        :: "r"(mbar), "r"(parity) : "memory");
}

__device__ __forceinline__ void bulk_load(uint32_t dst_smem, const void* src_gmem,
                                          uint32_t bytes, uint32_t mbar)
{
    asm volatile(
        "cp.async.bulk.shared::cta.global.mbarrier::complete_tx::bytes "
        "[%0], [%1], %2, [%3];"
        :: "r"(dst_smem), "l"(src_gmem), "r"(bytes), "r"(mbar) : "memory");
}

__device__ __forceinline__ void bulk_store(void* dst_gmem, uint32_t src_smem,
                                           uint32_t bytes)
{
    asm volatile(
        "cp.async.bulk.global.shared::cta.bulk_group [%0], [%1], %2;"
        :: "l"(dst_gmem), "r"(src_smem), "r"(bytes) : "memory");
}

__device__ __forceinline__ void store_commit()
{
    asm volatile("cp.async.bulk.commit_group;" ::: "memory");
}

template <int N>
__device__ __forceinline__ void store_wait()
{
    asm volatile("cp.async.bulk.wait_group %0;" :: "n"(N) : "memory");
}

__device__ __forceinline__ void issue_chunk_loads(const int* __restrict__ ids,
                                                  const char* __restrict__ emb,
                                                  int chunk, uint32_t stage_smem,
                                                  uint32_t mbar)
{
    // 8 row ids, two 16B loads.
    const int4* p = reinterpret_cast<const int4*>(ids + chunk * CHUNK_ROWS);
    int4 i0 = __ldg(p);
    int4 i1 = __ldg(p + 1);

    mbar_expect_tx(mbar, CHUNK_BYTES);

    bulk_load(stage_smem + 0 * ROW_BYTES, emb + (size_t)i0.x * ROW_BYTES, ROW_BYTES, mbar);
    bulk_load(stage_smem + 1 * ROW_BYTES, emb + (size_t)i0.y * ROW_BYTES, ROW_BYTES, mbar);
    bulk_load(stage_smem + 2 * ROW_BYTES, emb + (size_t)i0.z * ROW_BYTES, ROW_BYTES, mbar);
    bulk_load(stage_smem + 3 * ROW_BYTES, emb + (size_t)i0.w * ROW_BYTES, ROW_BYTES, mbar);
    bulk_load(stage_smem + 4 * ROW_BYTES, emb + (size_t)i1.x * ROW_BYTES, ROW_BYTES, mbar);
    bulk_load(stage_smem + 5 * ROW_BYTES, emb + (size_t)i1.y * ROW_BYTES, ROW_BYTES, mbar);
    bulk_load(stage_smem + 6 * ROW_BYTES, emb + (size_t)i1.z * ROW_BYTES, ROW_BYTES, mbar);
    bulk_load(stage_smem + 7 * ROW_BYTES, emb + (size_t)i1.w * ROW_BYTES, ROW_BYTES, mbar);
}

__global__ void __launch_bounds__(32)
hash_embedding_tma(const int* __restrict__ hashed_ids,
                   const char* __restrict__ emb,
                   char* __restrict__ out,
                   int nchunks)
{
    extern __shared__ char smem[];

    if (threadIdx.x != 0) return;

    const uint32_t base = smem_u32(smem);
    const int bid  = blockIdx.x;
    const int grid = gridDim.x;

    // Number of chunks this CTA owns (strided: bid, bid+grid, ...).
    int nmine = (nchunks - bid + grid - 1) / grid;
    if (nmine <= 0) return;

    // Init one mbarrier per stage.
    for (int s = 0; s < NSTAGES; s++)
        mbar_init(base + 8 * s, 1);
    asm volatile("fence.proxy.async.shared::cta;" ::: "memory");

    // Prefill up to NSTAGES chunks.
    int pre = nmine < NSTAGES ? nmine : NSTAGES;
    for (int s = 0; s < pre; s++) {
        int chunk = bid + s * grid;
        issue_chunk_loads(hashed_ids, emb, chunk,
                          base + STAGE_OFF + s * CHUNK_BYTES, base + 8 * s);
    }

    for (int k = 0; k < nmine; k++) {
        int s  = k % NSTAGES;
        int ph = (k / NSTAGES) & 1;
        int chunk = bid + k * grid;

        mbar_wait(base + 8 * s, ph);

        bulk_store(out + (size_t)chunk * CHUNK_BYTES,
                   base + STAGE_OFF + s * CHUNK_BYTES, CHUNK_BYTES);
        store_commit();

        // Refill the stage stored LAST iteration (its store is guaranteed
        // done once at most 1 newer group remains pending).
        int jk = k - 1 + NSTAGES;            // pipeline position to load
        if (k >= 1 && jk < nmine) {
            store_wait<1>();
            int sj = (k - 1) % NSTAGES;
            int jchunk = bid + jk * grid;
            issue_chunk_loads(hashed_ids, emb, jchunk,
                              base + STAGE_OFF + sj * CHUNK_BYTES, base + 8 * sj);
        }
    }

    store_wait<0>();
}

extern "C" void kernel_launch(void* const* d_in, const int* in_sizes, int n_in,
                              void* d_out, int out_size)
{
    // metadata order: input_ids (unused), hashed_ids (int32), embedding (fp32)
    const int*  hashed_ids = (const int*)d_in[1];
    const char* emb        = (const char*)d_in[2];
    char*       out        = (char*)d_out;

    int nrows   = in_sizes[1];                 // 32768
    int nchunks = nrows / CHUNK_ROWS;          // 4096

    static bool attr_set = false;
    if (!attr_set) {
        cudaFuncSetAttribute(hash_embedding_tma,
                             cudaFuncAttributeMaxDynamicSharedMemorySize,
                             SMEM_BYTES);
        attr_set = true;
    }

    hash_embedding_tma<<<CTAS, 32, SMEM_BYTES>>>(hashed_ids, emb, out, nchunks);
}